// round 2
// baseline (speedup 1.0000x reference)
#include <cuda_runtime.h>

// Problem constants (fixed by the dataset)
#define BB 128      // batch
#define GG 1024     // graph dim
#define KK 256      // kernel size
#define EE 128      // embed dim / 2
#define GSPLIT 4
#define BTILE 4

#define SCALE1 (0.001f / 1024.0f)   // beta / G
#define SCALE2 (0.001f / 128.0f)    // beta / E2

// ---------------- scratch (device globals; no allocation) ----------------
__device__ float g_c0p[GSPLIT * BB * KK];   // c0 partials over G-chunks
__device__ float g_nprp[GSPLIT * KK];       // ||P row k||^2 partials
__device__ float g_nimg[BB];                // ||img_b||^2
__device__ float g_nwrec[KK];               // sum_e w_rec[e,k]^2
__device__ float g_xp[BB * KK];             // final soft assignment
__device__ float g_part[BB * 8];            // loss partials per (b, g-chunk)

// block reduction over 256 threads (8 warps); s must hold 8 floats
__device__ __forceinline__ float blkred256(float v, bool ismax, float* s) {
#pragma unroll
    for (int o = 16; o > 0; o >>= 1) {
        float ov = __shfl_xor_sync(0xffffffffu, v, o);
        v = ismax ? fmaxf(v, ov) : (v + ov);
    }
    if ((threadIdx.x & 31) == 0) s[threadIdx.x >> 5] = v;
    __syncthreads();
    float r = s[0];
#pragma unroll
    for (int i = 1; i < 8; i++) r = ismax ? fmaxf(r, s[i]) : (r + s[i]);
    __syncthreads();
    return r;
}

// ---------------- K1: c0 partials + norms ----------------
// grid = 130 blocks x 512 threads.
// blocks [0,128): (bg, gs) tiles: 4 batch rows x 256-wide G chunk, all 256 k.
// block 128: ||img_b||^2 ; block 129: ||w_rec[:,k]||^2
__global__ void __launch_bounds__(512) k1_precompute(
    const float* __restrict__ img,
    const float* __restrict__ P,
    const float* __restrict__ wrec) {
    __shared__ __align__(16) float s_img[BTILE * 256];
    __shared__ float s_acc[2 * BTILE * 256];
    __shared__ float s_n[2 * 256];
    const int t = threadIdx.x;
    const int blk = blockIdx.x;

    if (blk < 128) {
        const int bg = blk >> 2, gs = blk & 3;
        const int b0 = bg * BTILE, g0 = gs * 256;
        for (int idx = t; idx < BTILE * 256; idx += 512) {
            int b = idx >> 8, gi = idx & 255;
            s_img[idx] = img[(size_t)(b0 + b) * GG + g0 + gi];
        }
        __syncthreads();

        const int k = t & 255, gh = t >> 8;  // gh: which 128-wide half
        const float* prow = P + (size_t)k * GG + g0 + gh * 128;
        const float* i0 = s_img + 0 * 256 + gh * 128;
        const float* i1 = s_img + 1 * 256 + gh * 128;
        const float* i2 = s_img + 2 * 256 + gh * 128;
        const float* i3 = s_img + 3 * 256 + gh * 128;
        float a0 = 0.f, a1 = 0.f, a2 = 0.f, a3 = 0.f, an = 0.f;
#pragma unroll 4
        for (int j = 0; j < 128; j += 4) {
            float4 pv = *(const float4*)(prow + j);
            an += pv.x * pv.x + pv.y * pv.y + pv.z * pv.z + pv.w * pv.w;
            float4 v0 = *(const float4*)(i0 + j);
            a0 += pv.x * v0.x + pv.y * v0.y + pv.z * v0.z + pv.w * v0.w;
            float4 v1 = *(const float4*)(i1 + j);
            a1 += pv.x * v1.x + pv.y * v1.y + pv.z * v1.z + pv.w * v1.w;
            float4 v2 = *(const float4*)(i2 + j);
            a2 += pv.x * v2.x + pv.y * v2.y + pv.z * v2.z + pv.w * v2.w;
            float4 v3 = *(const float4*)(i3 + j);
            a3 += pv.x * v3.x + pv.y * v3.y + pv.z * v3.z + pv.w * v3.w;
        }
        s_acc[(gh * BTILE + 0) * 256 + k] = a0;
        s_acc[(gh * BTILE + 1) * 256 + k] = a1;
        s_acc[(gh * BTILE + 2) * 256 + k] = a2;
        s_acc[(gh * BTILE + 3) * 256 + k] = a3;
        s_n[gh * 256 + k] = an;
        __syncthreads();
        if (gh == 0) {  // threads 0..255, t == k
#pragma unroll
            for (int b = 0; b < BTILE; b++) {
                g_c0p[(gs * BB + b0 + b) * KK + k] =
                    s_acc[b * 256 + k] + s_acc[(BTILE + b) * 256 + k];
            }
            if (bg == 0) g_nprp[gs * KK + k] = s_n[k] + s_n[256 + k];
        }
    } else if (blk == 128) {
        // ||img_b||^2: 4 threads per row, shuffle-combine
        const int b = t >> 2, q = t & 3;
        const float* r = img + (size_t)b * GG + q * 256;
        float a = 0.f;
#pragma unroll 4
        for (int j = 0; j < 256; j += 4) {
            float4 v = *(const float4*)(r + j);
            a += v.x * v.x + v.y * v.y + v.z * v.z + v.w * v.w;
        }
        a += __shfl_xor_sync(0xffffffffu, a, 1);
        a += __shfl_xor_sync(0xffffffffu, a, 2);
        if (q == 0) g_nimg[b] = a;
    } else {
        // nwrec[k] = sum_e w_rec[e*K + k]^2 (coalesced over k)
        if (t < KK) {
            float a = 0.f;
#pragma unroll 8
            for (int e = 0; e < EE; e++) {
                float v = wrec[e * KK + t];
                a += v * v;
            }
            g_nwrec[t] = a;
        }
    }
}

// ---------------- K2: per-row encode (softmax -> lat -> softmax) ----------
// grid = 128 blocks (one per batch row) x 256 threads (one per k)
__global__ void __launch_bounds__(256) k2_encode(const float* __restrict__ wrec) {
    __shared__ __align__(16) float s_p[256];
    __shared__ __align__(16) float s_lat[128];
    __shared__ float s_tmp[256];
    __shared__ float s_red[8];
    const int b = blockIdx.x, t = threadIdx.x;

    // combine c0 / norm partials
    float c0 = 0.f, npr = 0.f;
#pragma unroll
    for (int gs = 0; gs < GSPLIT; gs++) {
        c0 += g_c0p[(gs * BB + b) * KK + t];
        npr += g_nprp[gs * KK + t];
    }
    float nimg = g_nimg[b];

    // softmax over k of -beta/G * (||img||^2 - 2 c0 + ||P_k||^2)
    float logit = -SCALE1 * (nimg - 2.f * c0 + npr);
    float mx = blkred256(logit, true, s_red);
    float ev = __expf(logit - mx);
    float sum = blkred256(ev, false, s_red);
    s_p[t] = ev / sum;
    __syncthreads();

    // lat[e] = sum_k p[k] * w_rec[e, k]   (split k in two halves per thread)
    {
        const int e = t & 127, half = t >> 7, k0 = half * 128;
        const float* wr = wrec + (size_t)e * KK + k0;
        const float* pp = s_p + k0;
        float acc = 0.f;
#pragma unroll 8
        for (int k = 0; k < 128; k += 4) {
            float4 w = *(const float4*)(wr + k);
            float4 pv = *(const float4*)(pp + k);
            acc += w.x * pv.x + w.y * pv.y + w.z * pv.z + w.w * pv.w;
        }
        s_tmp[t] = acc;
    }
    __syncthreads();
    float nlat_part = 0.f;
    if (t < 128) {
        float lv = s_tmp[t] + s_tmp[128 + t];
        s_lat[t] = lv;
        nlat_part = lv * lv;
    }
    float nlat = blkred256(nlat_part, false, s_red);  // syncs make s_lat visible

    // dot2[k] = sum_e lat[e] * w_rec[e, k]  (coalesced over k = t)
    float acc = 0.f;
#pragma unroll 8
    for (int e = 0; e < EE; e++) acc += s_lat[e] * wrec[(size_t)e * KK + t];

    float logit2 = -SCALE2 * (nlat - 2.f * acc + g_nwrec[t]);
    float mx2 = blkred256(logit2, true, s_red);
    float e2 = __expf(logit2 - mx2);
    float s2 = blkred256(e2, false, s_red);
    g_xp[b * KK + t] = e2 / s2;
}

// ---------------- K3: rec = xp @ P, fused squared-error partials ----------
// grid = 128 blocks (16 b-tiles x 8 g-chunks) x 256 threads.
// warp w of a block owns row b0+w across a 128-wide g-chunk (lane = 4 cols).
__global__ void __launch_bounds__(256) k3_decode(
    const float* __restrict__ P, const float* __restrict__ img) {
    __shared__ __align__(16) float s_xp[8 * 256];
    const int blk = blockIdx.x;
    const int bt = blk >> 3, gc = blk & 7;
    const int b0 = bt * 8, g0 = gc * 128;
    const int t = threadIdx.x;

    for (int idx = t; idx < 8 * 256; idx += 256) {
        int row = idx >> 8;
        s_xp[idx] = g_xp[(b0 + row) * KK + (idx & 255)];
    }
    __syncthreads();

    const int w = t >> 5, l = t & 31;
    const int b = b0 + w;
    const int g = g0 + l * 4;
    const float* xr = s_xp + w * 256;
    float4 acc = make_float4(0.f, 0.f, 0.f, 0.f);
#pragma unroll 4
    for (int k = 0; k < 256; k += 4) {
        float4 xp4 = *(const float4*)(xr + k);
        float4 p0 = *(const float4*)(P + (size_t)(k + 0) * GG + g);
        acc.x += xp4.x * p0.x; acc.y += xp4.x * p0.y;
        acc.z += xp4.x * p0.z; acc.w += xp4.x * p0.w;
        float4 p1 = *(const float4*)(P + (size_t)(k + 1) * GG + g);
        acc.x += xp4.y * p1.x; acc.y += xp4.y * p1.y;
        acc.z += xp4.y * p1.z; acc.w += xp4.y * p1.w;
        float4 p2 = *(const float4*)(P + (size_t)(k + 2) * GG + g);
        acc.x += xp4.z * p2.x; acc.y += xp4.z * p2.y;
        acc.z += xp4.z * p2.z; acc.w += xp4.z * p2.w;
        float4 p3 = *(const float4*)(P + (size_t)(k + 3) * GG + g);
        acc.x += xp4.w * p3.x; acc.y += xp4.w * p3.y;
        acc.z += xp4.w * p3.z; acc.w += xp4.w * p3.w;
    }
    float4 iv = *(const float4*)(img + (size_t)b * GG + g);
    float dx = acc.x - iv.x, dy = acc.y - iv.y;
    float dz = acc.z - iv.z, dw = acc.w - iv.w;
    float ss = dx * dx + dy * dy + dz * dz + dw * dw;
#pragma unroll
    for (int o = 16; o > 0; o >>= 1) ss += __shfl_xor_sync(0xffffffffu, ss, o);
    if (l == 0) g_part[b * 8 + gc] = ss;
}

// ---------------- K4: final per-row loss ----------------
__global__ void k4_final(float* __restrict__ out) {
    const int t = threadIdx.x;
    if (t < BB) {
        float s = 0.f;
#pragma unroll
        for (int c = 0; c < 8; c++) s += g_part[t * 8 + c];
        out[t] = s * (1.0f / GG);
    }
}

extern "C" void kernel_launch(void* const* d_in, const int* in_sizes, int n_in,
                              void* d_out, int out_size) {
    // Identify inputs by element count (robust to ordering):
    // images 128*1024=131072, w_project 256*1024=262144, w_rec 128*256=32768.
    // w_img2 (33554432 elems) is dead code w.r.t. the output — never read.
    const float* img = nullptr;
    const float* P = nullptr;
    const float* wrec = nullptr;
    for (int i = 0; i < n_in; i++) {
        if (in_sizes[i] == BB * GG) img = (const float*)d_in[i];
        else if (in_sizes[i] == KK * GG) P = (const float*)d_in[i];
        else if (in_sizes[i] == EE * KK) wrec = (const float*)d_in[i];
    }
    float* out = (float*)d_out;

    k1_precompute<<<130, 512>>>(img, P, wrec);
    k2_encode<<<128, 256>>>(wrec);
    k3_decode<<<128, 256>>>(P, img);
    k4_final<<<1, 128>>>(out);
}